// round 1
// baseline (speedup 1.0000x reference)
#include <cuda_runtime.h>
#include <cuda_bf16.h>
#include <cstdint>

#define N_NODES 40000
#define N_EDGES 640000
#define DIN 128

// Scratch: intermediate feature buffers + CSR row pointers.
__device__ float g_h1[N_NODES * 128];
__device__ float g_h2[N_NODES * 128];
__device__ int   g_row_ptr[N_NODES + 1];

// row_ptr[n] = first index i in (sorted) dst with dst[i] >= n.
// row_ptr[N_NODES] = E (all dst < N_NODES).
__global__ void build_row_ptr_kernel(const int* __restrict__ dst) {
    int n = blockIdx.x * blockDim.x + threadIdx.x;
    if (n > N_NODES) return;
    int lo = 0, hi = N_EDGES;
    while (lo < hi) {
        int mid = (lo + hi) >> 1;
        if (dst[mid] < n) lo = mid + 1;
        else hi = mid;
    }
    g_row_ptr[n] = lo;
}

// Fused GIN layer: agg[n,:] = sum_{e: dst[e]==n} h_in[src[e],:]  then  out = agg @ W.
// Block = 512 threads = 4 nodes. Gather phase: threads nb*128..nb*128+127 accumulate
// node nb's row (col = tid&127) in a register. GEMM phase: thread (nb, j) computes
// one output element with the agg row staged in shared memory.
template <int DOUT>
__global__ void __launch_bounds__(512, 4)
gin_layer_kernel(const int* __restrict__ src,
                 const float* __restrict__ h_in,
                 const float* __restrict__ W,
                 float* __restrict__ h_out) {
    __shared__ float s[4 * DIN];

    const int tid = threadIdx.x;
    const int nb  = tid >> 7;        // 0..3, node within block
    const int col = tid & 127;       // feature column
    const int n   = blockIdx.x * 4 + nb;

    // ---- gather / segment-sum ----
    float acc = 0.f;
    if (n < N_NODES) {
        const int beg = g_row_ptr[n];
        const int end = g_row_ptr[n + 1];
        int e = beg;
        // unroll x4 for memory-level parallelism (all loads are L2 hits)
        for (; e + 3 < end; e += 4) {
            const int s0 = __ldg(&src[e]);
            const int s1 = __ldg(&src[e + 1]);
            const int s2 = __ldg(&src[e + 2]);
            const int s3 = __ldg(&src[e + 3]);
            float a0 = __ldg(&h_in[(size_t)s0 * DIN + col]);
            float a1 = __ldg(&h_in[(size_t)s1 * DIN + col]);
            float a2 = __ldg(&h_in[(size_t)s2 * DIN + col]);
            float a3 = __ldg(&h_in[(size_t)s3 * DIN + col]);
            acc += (a0 + a1) + (a2 + a3);
        }
        for (; e < end; ++e) {
            acc += __ldg(&h_in[(size_t)__ldg(&src[e]) * DIN + col]);
        }
    }
    s[tid] = acc;
    __syncthreads();

    // ---- dense GEMM: out[n, j] = sum_k s[nb*128+k] * W[k*DOUT + j] ----
    if (n < N_NODES && col < DOUT) {
        const int j = col;
        const float* srow = &s[nb * DIN];
        float o0 = 0.f, o1 = 0.f, o2 = 0.f, o3 = 0.f;
        #pragma unroll
        for (int k = 0; k < DIN; k += 4) {
            o0 += srow[k + 0] * __ldg(&W[(size_t)(k + 0) * DOUT + j]);
            o1 += srow[k + 1] * __ldg(&W[(size_t)(k + 1) * DOUT + j]);
            o2 += srow[k + 2] * __ldg(&W[(size_t)(k + 2) * DOUT + j]);
            o3 += srow[k + 3] * __ldg(&W[(size_t)(k + 3) * DOUT + j]);
        }
        h_out[(size_t)n * DOUT + j] = (o0 + o1) + (o2 + o3);
    }
}

extern "C" void kernel_launch(void* const* d_in, const int* in_sizes, int n_in,
                              void* d_out, int out_size) {
    const int*   src      = (const int*)d_in[0];
    const int*   dst      = (const int*)d_in[1];
    const float* features = (const float*)d_in[2];
    const float* W1       = (const float*)d_in[3];
    const float* W2       = (const float*)d_in[4];
    const float* W3       = (const float*)d_in[5];
    float*       out      = (float*)d_out;

    float* h1;
    float* h2;
    cudaGetSymbolAddress((void**)&h1, g_h1);
    cudaGetSymbolAddress((void**)&h2, g_h2);

    build_row_ptr_kernel<<<(N_NODES + 1 + 255) / 256, 256>>>(dst);

    const int blocks = (N_NODES + 3) / 4;  // 10000
    gin_layer_kernel<128><<<blocks, 512>>>(src, features, W1, h1);
    gin_layer_kernel<128><<<blocks, 512>>>(src, h1, W2, h2);
    gin_layer_kernel<64 ><<<blocks, 512>>>(src, h2, W3, out);
}

// round 2
// speedup vs baseline: 3.3800x; 3.3800x over previous
#include <cuda_runtime.h>
#include <cuda_bf16.h>
#include <cstdint>

#define N_NODES 40000
#define N_EDGES 640000
#define DIN 128
#define DOUT 64

// Scratch buffers (no allocations allowed in kernel_launch).
__device__ float g_t0[N_NODES * DOUT];   // h @ Wc, then hop results ping-pong
__device__ float g_t1[N_NODES * DOUT];
__device__ float g_W12[DIN * DIN];       // W1 @ W2
__device__ float g_Wc[DIN * DOUT];       // W12 @ W3
__device__ int   g_row_ptr[N_NODES + 1];

// row_ptr[n] = lower_bound(dst, n); dst is sorted.
__global__ void build_row_ptr_kernel(const int* __restrict__ dst) {
    int n = blockIdx.x * blockDim.x + threadIdx.x;
    if (n > N_NODES) return;
    int lo = 0, hi = N_EDGES;
    while (lo < hi) {
        int mid = (lo + hi) >> 1;
        if (dst[mid] < n) lo = mid + 1;
        else hi = mid;
    }
    g_row_ptr[n] = lo;
}

// W12 = W1(128x128) @ W2(128x128). grid=128 blocks (one row), 128 threads (one col).
__global__ void wc1_kernel(const float* __restrict__ W1, const float* __restrict__ W2) {
    __shared__ float row[DIN];
    const int i = blockIdx.x, j = threadIdx.x;
    row[j] = W1[i * DIN + j];
    __syncthreads();
    float acc = 0.f;
    #pragma unroll 8
    for (int k = 0; k < DIN; ++k) acc += row[k] * W2[k * DIN + j];
    g_W12[i * DIN + j] = acc;
}

// Wc = W12(128x128) @ W3(128x64). grid=128 blocks, 64 threads.
__global__ void wc2_kernel(const float* __restrict__ W3) {
    __shared__ float row[DIN];
    const int i = blockIdx.x, j = threadIdx.x;
    row[j] = g_W12[i * DIN + j];
    row[j + 64] = g_W12[i * DIN + j + 64];
    __syncthreads();
    float acc = 0.f;
    #pragma unroll 8
    for (int k = 0; k < DIN; ++k) acc += row[k] * W3[k * DOUT + j];
    g_Wc[i * DOUT + j] = acc;
}

// out[N,64] = F[N,128] @ Wc[128,64].
// Block: 512 threads, 64 nodes. Thread (ty=tid>>5 in 0..15, tx=tid&31):
// computes 4 nodes (ty+16r) x 2 cols (tx, tx+32) = 8 outputs.
// Per k: 4 broadcast LDS (F rows) + 2 conflict-free LDS (W) + 8 FFMA.
__global__ void __launch_bounds__(512)
gemm_fwc_kernel(const float* __restrict__ F, float* __restrict__ out) {
    __shared__ float sF[64 * DIN];   // 32 KB
    __shared__ float sW[DIN * DOUT]; // 32 KB

    const int tid = threadIdx.x;
    const int n0 = blockIdx.x * 64;

    // Cooperative loads, fully coalesced.
    #pragma unroll
    for (int i = 0; i < 16; ++i)
        sF[tid + i * 512] = F[(size_t)n0 * DIN + tid + i * 512];
    #pragma unroll
    for (int i = 0; i < 16; ++i)
        sW[tid + i * 512] = g_Wc[tid + i * 512];
    __syncthreads();

    const int tx = tid & 31;
    const int ty = tid >> 5;

    float acc[4][2] = {};
    #pragma unroll 8
    for (int k = 0; k < DIN; ++k) {
        const float w0 = sW[k * DOUT + tx];
        const float w1 = sW[k * DOUT + tx + 32];
        #pragma unroll
        for (int r = 0; r < 4; ++r) {
            const float f = sF[(ty + 16 * r) * DIN + k];
            acc[r][0] += f * w0;
            acc[r][1] += f * w1;
        }
    }
    #pragma unroll
    for (int r = 0; r < 4; ++r) {
        const int n = n0 + ty + 16 * r;
        out[(size_t)n * DOUT + tx]      = acc[r][0];
        out[(size_t)n * DOUT + tx + 32] = acc[r][1];
    }
}

// One aggregation hop at width 64: out[n,:] = sum_{e: dst[e]==n} in[src[e],:].
// Block: 512 threads = 8 nodes x 64 cols. Edge loop unrolled x4 for MLP.
__global__ void __launch_bounds__(512)
gather64_kernel(const int* __restrict__ src,
                const float* __restrict__ h_in,
                float* __restrict__ h_out) {
    const int tid = threadIdx.x;
    const int nb  = tid >> 6;      // 0..7
    const int col = tid & 63;
    const int n   = blockIdx.x * 8 + nb;
    if (n >= N_NODES) return;

    const int beg = g_row_ptr[n];
    const int end = g_row_ptr[n + 1];

    float acc = 0.f;
    int e = beg;
    for (; e + 3 < end; e += 4) {
        const int s0 = __ldg(&src[e]);
        const int s1 = __ldg(&src[e + 1]);
        const int s2 = __ldg(&src[e + 2]);
        const int s3 = __ldg(&src[e + 3]);
        float a0 = __ldg(&h_in[(size_t)s0 * DOUT + col]);
        float a1 = __ldg(&h_in[(size_t)s1 * DOUT + col]);
        float a2 = __ldg(&h_in[(size_t)s2 * DOUT + col]);
        float a3 = __ldg(&h_in[(size_t)s3 * DOUT + col]);
        acc += (a0 + a1) + (a2 + a3);
    }
    for (; e < end; ++e)
        acc += __ldg(&h_in[(size_t)__ldg(&src[e]) * DOUT + col]);

    h_out[(size_t)n * DOUT + col] = acc;
}

extern "C" void kernel_launch(void* const* d_in, const int* in_sizes, int n_in,
                              void* d_out, int out_size) {
    const int*   src      = (const int*)d_in[0];
    const int*   dst      = (const int*)d_in[1];
    const float* features = (const float*)d_in[2];
    const float* W1       = (const float*)d_in[3];
    const float* W2       = (const float*)d_in[4];
    const float* W3       = (const float*)d_in[5];
    float*       out      = (float*)d_out;

    float* t0; float* t1;
    cudaGetSymbolAddress((void**)&t0, g_t0);
    cudaGetSymbolAddress((void**)&t1, g_t1);

    build_row_ptr_kernel<<<(N_NODES + 1 + 255) / 256, 256>>>(dst);
    wc1_kernel<<<DIN, DIN>>>(W1, W2);
    wc2_kernel<<<DIN, DOUT>>>(W3);

    // h' = features @ Wc   (40000 x 64)
    gemm_fwc_kernel<<<N_NODES / 64, 512>>>(features, t0);

    // out = A^3 h'
    gather64_kernel<<<N_NODES / 8, 512>>>(src, t0, t1);
    gather64_kernel<<<N_NODES / 8, 512>>>(src, t1, t0);
    gather64_kernel<<<N_NODES / 8, 512>>>(src, t0, out);
}

// round 3
// speedup vs baseline: 4.3995x; 1.3016x over previous
#include <cuda_runtime.h>
#include <cuda_bf16.h>
#include <cstdint>

#define N_NODES 40000
#define N_EDGES 640000
#define DIN 128
#define DOUT 64

__device__ float g_t0[N_NODES * DOUT];
__device__ float g_t1[N_NODES * DOUT];
__device__ float g_W12[DIN * DIN];
__device__ float g_Wc[DIN * DOUT];
__device__ int   g_row_ptr[N_NODES + 1];

// row_ptr[n] = lower_bound(dst, n); dst is sorted.
__global__ void build_row_ptr_kernel(const int* __restrict__ dst) {
    int n = blockIdx.x * blockDim.x + threadIdx.x;
    if (n > N_NODES) return;
    int lo = 0, hi = N_EDGES;
    while (lo < hi) {
        int mid = (lo + hi) >> 1;
        if (dst[mid] < n) lo = mid + 1;
        else hi = mid;
    }
    g_row_ptr[n] = lo;
}

// W12 = W1 @ W2 (128x128 @ 128x128)
__global__ void wc1_kernel(const float* __restrict__ W1, const float* __restrict__ W2) {
    __shared__ float row[DIN];
    const int i = blockIdx.x, j = threadIdx.x;
    row[j] = W1[i * DIN + j];
    __syncthreads();
    float acc = 0.f;
    #pragma unroll 8
    for (int k = 0; k < DIN; ++k) acc += row[k] * W2[k * DIN + j];
    g_W12[i * DIN + j] = acc;
}

// Wc = W12 @ W3 (128x128 @ 128x64)
__global__ void wc2_kernel(const float* __restrict__ W3) {
    __shared__ float row[DIN];
    const int i = blockIdx.x, j = threadIdx.x;
    row[j] = g_W12[i * DIN + j];
    row[j + 64] = g_W12[i * DIN + j + 64];
    __syncthreads();
    float acc = 0.f;
    #pragma unroll 8
    for (int k = 0; k < DIN; ++k) acc += row[k] * W3[k * DOUT + j];
    g_Wc[i * DOUT + j] = acc;
}

// out[N,64] = F[N,128] @ Wc[128,64].
// 256 threads, tile = 64 nodes x 64 cols, each thread a 4x4 micro-tile.
// Per k: 1 LDS.128 (W quad) + 4 broadcast scalar LDS (F) -> 16 FFMA.
__global__ void __launch_bounds__(256)
gemm_fwc_kernel(const float* __restrict__ F, float* __restrict__ out) {
    __shared__ float sF[64 * DIN];   // [node][k], 32 KB
    __shared__ float sW[DIN * DOUT]; // [k][col],  32 KB

    const int tid = threadIdx.x;
    const int n0 = blockIdx.x * 64;

    // Cooperative coalesced loads (float4).
    const float4* F4 = (const float4*)(F + (size_t)n0 * DIN);
    float4* sF4 = (float4*)sF;
    #pragma unroll
    for (int i = 0; i < 8; ++i)
        sF4[tid + i * 256] = F4[tid + i * 256];
    const float4* W4 = (const float4*)g_Wc;
    float4* sW4 = (float4*)sW;
    #pragma unroll
    for (int i = 0; i < 8; ++i)
        sW4[tid + i * 256] = W4[tid + i * 256];
    __syncthreads();

    const int tx = tid & 15;        // col group: cols 4*tx .. 4*tx+3
    const int ty = tid >> 4;        // node group: nodes 4*ty .. 4*ty+3
    const int cj = tx * 4;
    const int ni = ty * 4;

    float acc[4][4] = {};
    #pragma unroll 4
    for (int k = 0; k < DIN; ++k) {
        const float4 w = *(const float4*)&sW[k * DOUT + cj];
        #pragma unroll
        for (int i = 0; i < 4; ++i) {
            const float f = sF[(ni + i) * DIN + k];
            acc[i][0] += f * w.x;
            acc[i][1] += f * w.y;
            acc[i][2] += f * w.z;
            acc[i][3] += f * w.w;
        }
    }
    #pragma unroll
    for (int i = 0; i < 4; ++i) {
        float4 o = make_float4(acc[i][0], acc[i][1], acc[i][2], acc[i][3]);
        *(float4*)&out[(size_t)(n0 + ni + i) * DOUT + cj] = o;
    }
}

// One aggregation hop at width 64 with float4 lanes:
// 512 threads = 32 nodes x 16 lanes; each lane owns 4 contiguous floats.
__global__ void __launch_bounds__(512)
gather64_kernel(const int* __restrict__ src,
                const float* __restrict__ h_in,
                float* __restrict__ h_out) {
    const int tid  = threadIdx.x;
    const int lane = tid & 15;     // float4 index within row (16 * 4 = 64)
    const int nb   = tid >> 4;     // 0..31
    const int n    = blockIdx.x * 32 + nb;
    if (n >= N_NODES) return;

    const float4* in4 = (const float4*)h_in;
    const int beg = g_row_ptr[n];
    const int end = g_row_ptr[n + 1];

    float4 acc = make_float4(0.f, 0.f, 0.f, 0.f);
    int e = beg;
    for (; e + 3 < end; e += 4) {
        const int s0 = __ldg(&src[e]);
        const int s1 = __ldg(&src[e + 1]);
        const int s2 = __ldg(&src[e + 2]);
        const int s3 = __ldg(&src[e + 3]);
        float4 a0 = __ldg(&in4[(size_t)s0 * 16 + lane]);
        float4 a1 = __ldg(&in4[(size_t)s1 * 16 + lane]);
        float4 a2 = __ldg(&in4[(size_t)s2 * 16 + lane]);
        float4 a3 = __ldg(&in4[(size_t)s3 * 16 + lane]);
        acc.x += (a0.x + a1.x) + (a2.x + a3.x);
        acc.y += (a0.y + a1.y) + (a2.y + a3.y);
        acc.z += (a0.z + a1.z) + (a2.z + a3.z);
        acc.w += (a0.w + a1.w) + (a2.w + a3.w);
    }
    for (; e < end; ++e) {
        float4 a = __ldg(&in4[(size_t)__ldg(&src[e]) * 16 + lane]);
        acc.x += a.x; acc.y += a.y; acc.z += a.z; acc.w += a.w;
    }

    ((float4*)h_out)[(size_t)n * 16 + lane] = acc;
}

extern "C" void kernel_launch(void* const* d_in, const int* in_sizes, int n_in,
                              void* d_out, int out_size) {
    const int*   src      = (const int*)d_in[0];
    const int*   dst      = (const int*)d_in[1];
    const float* features = (const float*)d_in[2];
    const float* W1       = (const float*)d_in[3];
    const float* W2       = (const float*)d_in[4];
    const float* W3       = (const float*)d_in[5];
    float*       out      = (float*)d_out;

    float* t0; float* t1;
    cudaGetSymbolAddress((void**)&t0, g_t0);
    cudaGetSymbolAddress((void**)&t1, g_t1);

    build_row_ptr_kernel<<<(N_NODES + 1 + 255) / 256, 256>>>(dst);
    wc1_kernel<<<DIN, DIN>>>(W1, W2);
    wc2_kernel<<<DIN, DOUT>>>(W3);

    gemm_fwc_kernel<<<N_NODES / 64, 256>>>(features, t0);

    gather64_kernel<<<N_NODES / 32, 512>>>(src, t0, t1);
    gather64_kernel<<<N_NODES / 32, 512>>>(src, t1, t0);
    gather64_kernel<<<N_NODES / 32, 512>>>(src, t0, out);
}

// round 4
// speedup vs baseline: 4.4710x; 1.0163x over previous
#include <cuda_runtime.h>
#include <cuda_bf16.h>
#include <cstdint>

#define N_NODES 40000
#define N_EDGES 640000
#define DIN 128
#define DOUT 64

__device__ float g_t0[N_NODES * DOUT];
__device__ float g_t1[N_NODES * DOUT];
__device__ float g_Wc[DIN * DOUT];
__device__ int   g_row_ptr[N_NODES + 1];

// row_ptr[n] = lower_bound(dst, n); dst is sorted.
__global__ void build_row_ptr_kernel(const int* __restrict__ dst) {
    int n = blockIdx.x * blockDim.x + threadIdx.x;
    if (n > N_NODES) return;
    int lo = 0, hi = N_EDGES;
    while (lo < hi) {
        int mid = (lo + hi) >> 1;
        if (dst[mid] < n) lo = mid + 1;
        else hi = mid;
    }
    g_row_ptr[n] = lo;
}

// Wc = (W1 @ W2) @ W3 in one kernel. 128 blocks (one output row), 128 threads.
__global__ void __launch_bounds__(128)
wc_kernel(const float* __restrict__ W1, const float* __restrict__ W2,
          const float* __restrict__ W3) {
    __shared__ float sW2[DIN * DIN];   // 64 KB
    __shared__ float row[DIN];
    __shared__ float t1[DIN];

    const int i = blockIdx.x, j = threadIdx.x;

    // Stage W2 (coalesced float4).
    const float4* W24 = (const float4*)W2;
    float4* sW24 = (float4*)sW2;
    #pragma unroll
    for (int it = 0; it < 32; ++it)
        sW24[j + it * 128] = W24[j + it * 128];
    row[j] = W1[i * DIN + j];
    __syncthreads();

    float acc = 0.f;
    #pragma unroll 8
    for (int k = 0; k < DIN; ++k) acc += row[k] * sW2[k * DIN + j];
    t1[j] = acc;
    __syncthreads();

    if (j < DOUT) {
        float acc2 = 0.f;
        #pragma unroll 8
        for (int k = 0; k < DIN; ++k) acc2 += t1[k] * __ldg(&W3[k * DOUT + j]);
        g_Wc[i * DOUT + j] = acc2;
    }
}

// out[N,64] = F[N,128] @ Wc[128,64].
// 256 threads, tile = 64 nodes x 64 cols, 4x4 micro-tile, k chunked by 4:
// per chunk: 4 LDS.128 (W) + 4 LDS.128 (F, 2-addr broadcast) -> 64 FFMA.
__global__ void __launch_bounds__(256)
gemm_fwc_kernel(const float* __restrict__ F, float* __restrict__ out) {
    __shared__ float sF[64 * DIN];   // [node][k], 32 KB
    __shared__ float sW[DIN * DOUT]; // [k][col],  32 KB

    const int tid = threadIdx.x;
    const int n0 = blockIdx.x * 64;

    const float4* F4 = (const float4*)(F + (size_t)n0 * DIN);
    float4* sF4 = (float4*)sF;
    #pragma unroll
    for (int i = 0; i < 8; ++i)
        sF4[tid + i * 256] = F4[tid + i * 256];
    const float4* W4 = (const float4*)g_Wc;
    float4* sW4 = (float4*)sW;
    #pragma unroll
    for (int i = 0; i < 8; ++i)
        sW4[tid + i * 256] = W4[tid + i * 256];
    __syncthreads();

    const int tx = tid & 15;
    const int ty = tid >> 4;
    const int cj = tx * 4;
    const int ni = ty * 4;

    float acc[4][4] = {};
    #pragma unroll
    for (int k = 0; k < DIN; k += 4) {
        float4 w[4];
        #pragma unroll
        for (int j = 0; j < 4; ++j)
            w[j] = *(const float4*)&sW[(k + j) * DOUT + cj];
        float4 f[4];
        #pragma unroll
        for (int i = 0; i < 4; ++i)
            f[i] = *(const float4*)&sF[(ni + i) * DIN + k];
        #pragma unroll
        for (int i = 0; i < 4; ++i) {
            acc[i][0] += f[i].x * w[0].x + f[i].y * w[1].x + f[i].z * w[2].x + f[i].w * w[3].x;
            acc[i][1] += f[i].x * w[0].y + f[i].y * w[1].y + f[i].z * w[2].y + f[i].w * w[3].y;
            acc[i][2] += f[i].x * w[0].z + f[i].y * w[1].z + f[i].z * w[2].z + f[i].w * w[3].z;
            acc[i][3] += f[i].x * w[0].w + f[i].y * w[1].w + f[i].z * w[2].w + f[i].w * w[3].w;
        }
    }
    #pragma unroll
    for (int i = 0; i < 4; ++i) {
        float4 o = make_float4(acc[i][0], acc[i][1], acc[i][2], acc[i][3]);
        *(float4*)&out[(size_t)(n0 + ni + i) * DOUT + cj] = o;
    }
}

// One aggregation hop at width 64 with float4 lanes:
// 512 threads = 32 nodes x 16 lanes; each lane owns 4 contiguous floats.
__global__ void __launch_bounds__(512)
gather64_kernel(const int* __restrict__ src,
                const float* __restrict__ h_in,
                float* __restrict__ h_out) {
    const int tid  = threadIdx.x;
    const int lane = tid & 15;
    const int nb   = tid >> 4;
    const int n    = blockIdx.x * 32 + nb;
    if (n >= N_NODES) return;

    const float4* in4 = (const float4*)h_in;
    const int beg = g_row_ptr[n];
    const int end = g_row_ptr[n + 1];

    float4 acc = make_float4(0.f, 0.f, 0.f, 0.f);
    int e = beg;
    for (; e + 3 < end; e += 4) {
        const int s0 = __ldg(&src[e]);
        const int s1 = __ldg(&src[e + 1]);
        const int s2 = __ldg(&src[e + 2]);
        const int s3 = __ldg(&src[e + 3]);
        float4 a0 = __ldg(&in4[(size_t)s0 * 16 + lane]);
        float4 a1 = __ldg(&in4[(size_t)s1 * 16 + lane]);
        float4 a2 = __ldg(&in4[(size_t)s2 * 16 + lane]);
        float4 a3 = __ldg(&in4[(size_t)s3 * 16 + lane]);
        acc.x += (a0.x + a1.x) + (a2.x + a3.x);
        acc.y += (a0.y + a1.y) + (a2.y + a3.y);
        acc.z += (a0.z + a1.z) + (a2.z + a3.z);
        acc.w += (a0.w + a1.w) + (a2.w + a3.w);
    }
    if (e + 1 < end) {
        const int s0 = __ldg(&src[e]);
        const int s1 = __ldg(&src[e + 1]);
        float4 a0 = __ldg(&in4[(size_t)s0 * 16 + lane]);
        float4 a1 = __ldg(&in4[(size_t)s1 * 16 + lane]);
        acc.x += a0.x + a1.x; acc.y += a0.y + a1.y;
        acc.z += a0.z + a1.z; acc.w += a0.w + a1.w;
        e += 2;
    }
    if (e < end) {
        float4 a = __ldg(&in4[(size_t)__ldg(&src[e]) * 16 + lane]);
        acc.x += a.x; acc.y += a.y; acc.z += a.z; acc.w += a.w;
    }

    ((float4*)h_out)[(size_t)n * 16 + lane] = acc;
}

extern "C" void kernel_launch(void* const* d_in, const int* in_sizes, int n_in,
                              void* d_out, int out_size) {
    const int*   src      = (const int*)d_in[0];
    const int*   dst      = (const int*)d_in[1];
    const float* features = (const float*)d_in[2];
    const float* W1       = (const float*)d_in[3];
    const float* W2       = (const float*)d_in[4];
    const float* W3       = (const float*)d_in[5];
    float*       out      = (float*)d_out;

    float* t0; float* t1;
    cudaGetSymbolAddress((void**)&t0, g_t0);
    cudaGetSymbolAddress((void**)&t1, g_t1);

    build_row_ptr_kernel<<<(N_NODES + 1 + 255) / 256, 256>>>(dst);
    wc_kernel<<<DIN, DIN>>>(W1, W2, W3);

    gemm_fwc_kernel<<<N_NODES / 64, 256>>>(features, t0);

    gather64_kernel<<<N_NODES / 32, 512>>>(src, t0, t1);
    gather64_kernel<<<N_NODES / 32, 512>>>(src, t1, t0);
    gather64_kernel<<<N_NODES / 32, 512>>>(src, t0, out);
}

// round 5
// speedup vs baseline: 4.7213x; 1.0560x over previous
#include <cuda_runtime.h>
#include <cuda_bf16.h>
#include <cstdint>

#define N_NODES 40000
#define N_EDGES 640000
#define DIN 128
#define DOUT 64

__device__ float g_t0[N_NODES * DOUT];
__device__ float g_t1[N_NODES * DOUT];
__device__ float g_Wc[DIN * DOUT];
__device__ int   g_row_ptr[N_NODES + 1];

// row_ptr[n] = lower_bound(dst, n); dst is sorted.
__global__ void build_row_ptr_kernel(const int* __restrict__ dst) {
    int n = blockIdx.x * blockDim.x + threadIdx.x;
    if (n > N_NODES) return;
    int lo = 0, hi = N_EDGES;
    while (lo < hi) {
        int mid = (lo + hi) >> 1;
        if (dst[mid] < n) lo = mid + 1;
        else hi = mid;
    }
    g_row_ptr[n] = lo;
}

// Wc = (W1 @ W2) @ W3 in one kernel. 128 blocks (one output row), 128 threads.
__global__ void __launch_bounds__(128)
wc_kernel(const float* __restrict__ W1, const float* __restrict__ W2,
          const float* __restrict__ W3) {
    __shared__ float sW2[DIN * DIN];   // 64 KB
    __shared__ float row[DIN];
    __shared__ float t1[DIN];

    const int i = blockIdx.x, j = threadIdx.x;

    const float4* W24 = (const float4*)W2;
    float4* sW24 = (float4*)sW2;
    #pragma unroll
    for (int it = 0; it < 32; ++it)
        sW24[j + it * 128] = W24[j + it * 128];
    row[j] = W1[i * DIN + j];
    __syncthreads();

    float acc = 0.f;
    #pragma unroll 8
    for (int k = 0; k < DIN; ++k) acc += row[k] * sW2[k * DIN + j];
    t1[j] = acc;
    __syncthreads();

    if (j < DOUT) {
        float acc2 = 0.f;
        #pragma unroll 8
        for (int k = 0; k < DIN; ++k) acc2 += t1[k] * __ldg(&W3[k * DOUT + j]);
        g_Wc[i * DOUT + j] = acc2;
    }
}

// out[N,64] = F[N,128] @ Wc[128,64].
// 256 threads, 64x64 tile, 4x4 micro-tile, k chunked by 4 (all-LDS.128).
__global__ void __launch_bounds__(256)
gemm_fwc_kernel(const float* __restrict__ F, float* __restrict__ out) {
    __shared__ float sF[64 * DIN];
    __shared__ float sW[DIN * DOUT];

    const int tid = threadIdx.x;
    const int n0 = blockIdx.x * 64;

    const float4* F4 = (const float4*)(F + (size_t)n0 * DIN);
    float4* sF4 = (float4*)sF;
    #pragma unroll
    for (int i = 0; i < 8; ++i)
        sF4[tid + i * 256] = F4[tid + i * 256];
    const float4* W4 = (const float4*)g_Wc;
    float4* sW4 = (float4*)sW;
    #pragma unroll
    for (int i = 0; i < 8; ++i)
        sW4[tid + i * 256] = W4[tid + i * 256];
    __syncthreads();

    const int tx = tid & 15;
    const int ty = tid >> 4;
    const int cj = tx * 4;
    const int ni = ty * 4;

    float acc[4][4] = {};
    #pragma unroll
    for (int k = 0; k < DIN; k += 4) {
        float4 w[4];
        #pragma unroll
        for (int j = 0; j < 4; ++j)
            w[j] = *(const float4*)&sW[(k + j) * DOUT + cj];
        float4 f[4];
        #pragma unroll
        for (int i = 0; i < 4; ++i)
            f[i] = *(const float4*)&sF[(ni + i) * DIN + k];
        #pragma unroll
        for (int i = 0; i < 4; ++i) {
            acc[i][0] += f[i].x * w[0].x + f[i].y * w[1].x + f[i].z * w[2].x + f[i].w * w[3].x;
            acc[i][1] += f[i].x * w[0].y + f[i].y * w[1].y + f[i].z * w[2].y + f[i].w * w[3].y;
            acc[i][2] += f[i].x * w[0].z + f[i].y * w[1].z + f[i].z * w[2].z + f[i].w * w[3].z;
            acc[i][3] += f[i].x * w[0].w + f[i].y * w[1].w + f[i].z * w[2].w + f[i].w * w[3].w;
        }
    }
    #pragma unroll
    for (int i = 0; i < 4; ++i) {
        float4 o = make_float4(acc[i][0], acc[i][1], acc[i][2], acc[i][3]);
        *(float4*)&out[(size_t)(n0 + ni + i) * DOUT + cj] = o;
    }
}

// One aggregation hop at width 64: ONE WARP PER NODE.
// lane = (half, quad): half in {0,1} picks edge parity, quad picks float4 col.
// Per warp iteration: 8 edges x 4 LDG.128 per thread in flight.
// Halves merged at the end with 4 shfl_down.
__global__ void __launch_bounds__(256)
gather64_kernel(const int* __restrict__ src,
                const float* __restrict__ h_in,
                float* __restrict__ h_out) {
    const int n = blockIdx.x * 8 + (threadIdx.x >> 5);
    if (n >= N_NODES) return;

    const int lane = threadIdx.x & 31;
    const int quad = lane & 15;
    const int half = lane >> 4;

    const float4* in4 = (const float4*)h_in;
    const int beg = g_row_ptr[n];
    const int end = g_row_ptr[n + 1];

    float4 acc0 = make_float4(0.f, 0.f, 0.f, 0.f);
    float4 acc1 = make_float4(0.f, 0.f, 0.f, 0.f);

    int e = beg + half;                 // this half handles edges of its parity
    // main loop: 4 edges per thread per iter (8 warp-wide)
    for (; e + 6 < end; e += 8) {
        const int s0 = __ldg(&src[e]);
        const int s1 = __ldg(&src[e + 2]);
        const int s2 = __ldg(&src[e + 4]);
        const int s3 = __ldg(&src[e + 6]);
        float4 a0 = __ldg(&in4[(size_t)s0 * 16 + quad]);
        float4 a1 = __ldg(&in4[(size_t)s1 * 16 + quad]);
        float4 a2 = __ldg(&in4[(size_t)s2 * 16 + quad]);
        float4 a3 = __ldg(&in4[(size_t)s3 * 16 + quad]);
        acc0.x += a0.x + a1.x; acc1.x += a2.x + a3.x;
        acc0.y += a0.y + a1.y; acc1.y += a2.y + a3.y;
        acc0.z += a0.z + a1.z; acc1.z += a2.z + a3.z;
        acc0.w += a0.w + a1.w; acc1.w += a2.w + a3.w;
    }
    if (e + 2 < end) {
        const int s0 = __ldg(&src[e]);
        const int s1 = __ldg(&src[e + 2]);
        float4 a0 = __ldg(&in4[(size_t)s0 * 16 + quad]);
        float4 a1 = __ldg(&in4[(size_t)s1 * 16 + quad]);
        acc0.x += a0.x; acc1.x += a1.x;
        acc0.y += a0.y; acc1.y += a1.y;
        acc0.z += a0.z; acc1.z += a1.z;
        acc0.w += a0.w; acc1.w += a1.w;
        e += 4;
    }
    if (e < end) {
        float4 a = __ldg(&in4[(size_t)__ldg(&src[e]) * 16 + quad]);
        acc0.x += a.x; acc0.y += a.y; acc0.z += a.z; acc0.w += a.w;
    }

    float4 acc;
    acc.x = acc0.x + acc1.x;
    acc.y = acc0.y + acc1.y;
    acc.z = acc0.z + acc1.z;
    acc.w = acc0.w + acc1.w;

    // merge the two halves of the warp
    acc.x += __shfl_down_sync(0xffffffffu, acc.x, 16);
    acc.y += __shfl_down_sync(0xffffffffu, acc.y, 16);
    acc.z += __shfl_down_sync(0xffffffffu, acc.z, 16);
    acc.w += __shfl_down_sync(0xffffffffu, acc.w, 16);

    if (half == 0)
        ((float4*)h_out)[(size_t)n * 16 + quad] = acc;
}

extern "C" void kernel_launch(void* const* d_in, const int* in_sizes, int n_in,
                              void* d_out, int out_size) {
    const int*   src      = (const int*)d_in[0];
    const int*   dst      = (const int*)d_in[1];
    const float* features = (const float*)d_in[2];
    const float* W1       = (const float*)d_in[3];
    const float* W2       = (const float*)d_in[4];
    const float* W3       = (const float*)d_in[5];
    float*       out      = (float*)d_out;

    float* t0; float* t1;
    cudaGetSymbolAddress((void**)&t0, g_t0);
    cudaGetSymbolAddress((void**)&t1, g_t1);

    build_row_ptr_kernel<<<(N_NODES + 1 + 255) / 256, 256>>>(dst);
    wc_kernel<<<DIN, DIN>>>(W1, W2, W3);

    gemm_fwc_kernel<<<N_NODES / 64, 256>>>(features, t0);

    const int gblocks = (N_NODES + 7) / 8;   // 5000
    gather64_kernel<<<gblocks, 256>>>(src, t0, t1);
    gather64_kernel<<<gblocks, 256>>>(src, t1, t0);
    gather64_kernel<<<gblocks, 256>>>(src, t0, out);
}

// round 6
// speedup vs baseline: 4.8501x; 1.0273x over previous
#include <cuda_runtime.h>
#include <cuda_bf16.h>
#include <cstdint>

#define N_NODES 40000
#define N_EDGES 640000
#define DIN 128
#define DOUT 64

__device__ float g_t0[N_NODES * DOUT];
__device__ float g_t1[N_NODES * DOUT];
__device__ float g_Wc[DIN * DOUT];
__device__ int   g_row_ptr[N_NODES + 1];

// row_ptr[n] = lower_bound(dst, n); dst is sorted.
__global__ void build_row_ptr_kernel(const int* __restrict__ dst) {
    int n = blockIdx.x * blockDim.x + threadIdx.x;
    if (n > N_NODES) return;
    int lo = 0, hi = N_EDGES;
    while (lo < hi) {
        int mid = (lo + hi) >> 1;
        if (dst[mid] < n) lo = mid + 1;
        else hi = mid;
    }
    g_row_ptr[n] = lo;
}

// Wc = (W1 @ W2) @ W3 in one kernel. 128 blocks (one output row), 128 threads.
__global__ void __launch_bounds__(128)
wc_kernel(const float* __restrict__ W1, const float* __restrict__ W2,
          const float* __restrict__ W3) {
    __shared__ float sW2[DIN * DIN];
    __shared__ float row[DIN];
    __shared__ float t1[DIN];

    const int i = blockIdx.x, j = threadIdx.x;

    const float4* W24 = (const float4*)W2;
    float4* sW24 = (float4*)sW2;
    #pragma unroll
    for (int it = 0; it < 32; ++it)
        sW24[j + it * 128] = W24[j + it * 128];
    row[j] = W1[i * DIN + j];
    __syncthreads();

    float acc = 0.f;
    #pragma unroll 8
    for (int k = 0; k < DIN; ++k) acc += row[k] * sW2[k * DIN + j];
    t1[j] = acc;
    __syncthreads();

    if (j < DOUT) {
        float acc2 = 0.f;
        #pragma unroll 8
        for (int k = 0; k < DIN; ++k) acc2 += t1[k] * __ldg(&W3[k * DOUT + j]);
        g_Wc[i * DOUT + j] = acc2;
    }
}

// out[N,64] = F[N,128] @ Wc[128,64].
// 256 threads, 64x64 tile, 4x4 micro-tile, k chunked by 4 (all-LDS.128).
__global__ void __launch_bounds__(256)
gemm_fwc_kernel(const float* __restrict__ F, float* __restrict__ out) {
    __shared__ float sF[64 * DIN];
    __shared__ float sW[DIN * DOUT];

    const int tid = threadIdx.x;
    const int n0 = blockIdx.x * 64;

    const float4* F4 = (const float4*)(F + (size_t)n0 * DIN);
    float4* sF4 = (float4*)sF;
    #pragma unroll
    for (int i = 0; i < 8; ++i)
        sF4[tid + i * 256] = F4[tid + i * 256];
    const float4* W4 = (const float4*)g_Wc;
    float4* sW4 = (float4*)sW;
    #pragma unroll
    for (int i = 0; i < 8; ++i)
        sW4[tid + i * 256] = W4[tid + i * 256];
    __syncthreads();

    const int tx = tid & 15;
    const int ty = tid >> 4;
    const int cj = tx * 4;
    const int ni = ty * 4;

    float acc[4][4] = {};
    #pragma unroll
    for (int k = 0; k < DIN; k += 4) {
        float4 w[4];
        #pragma unroll
        for (int j = 0; j < 4; ++j)
            w[j] = *(const float4*)&sW[(k + j) * DOUT + cj];
        float4 f[4];
        #pragma unroll
        for (int i = 0; i < 4; ++i)
            f[i] = *(const float4*)&sF[(ni + i) * DIN + k];
        #pragma unroll
        for (int i = 0; i < 4; ++i) {
            acc[i][0] += f[i].x * w[0].x + f[i].y * w[1].x + f[i].z * w[2].x + f[i].w * w[3].x;
            acc[i][1] += f[i].x * w[0].y + f[i].y * w[1].y + f[i].z * w[2].y + f[i].w * w[3].y;
            acc[i][2] += f[i].x * w[0].z + f[i].y * w[1].z + f[i].z * w[2].z + f[i].w * w[3].z;
            acc[i][3] += f[i].x * w[0].w + f[i].y * w[1].w + f[i].z * w[2].w + f[i].w * w[3].w;
        }
    }
    #pragma unroll
    for (int i = 0; i < 4; ++i) {
        float4 o = make_float4(acc[i][0], acc[i][1], acc[i][2], acc[i][3]);
        *(float4*)&out[(size_t)(n0 + ni + i) * DOUT + cj] = o;
    }
}

// Aggregation hop, width 64. Block = 256 thr = 8 warps = 8 nodes.
// dst sorted => a block's edges [row_ptr[n0], row_ptr[n0+8]) are CONTIGUOUS.
// Stage src indices for the block into smem (coalesced, chunk=256), then the
// inner loop reads indices from smem (LDS) and issues only feature LDG.128s:
// critical path per iteration drops from ~2 L2 latencies to 1.
#define GCHUNK 256
__global__ void __launch_bounds__(256)
gather64_kernel(const int* __restrict__ src,
                const float* __restrict__ h_in,
                float* __restrict__ h_out) {
    __shared__ int s_idx[GCHUNK];

    const int tid  = threadIdx.x;
    const int wid  = tid >> 5;
    const int lane = tid & 31;
    const int quad = lane & 15;
    const int half = lane >> 4;

    const int n0 = blockIdx.x * 8;
    const int n  = n0 + wid;              // grid sized exactly: n < N_NODES

    const int blk_beg = g_row_ptr[n0];
    const int blk_end = g_row_ptr[n0 + 8];
    const int beg = g_row_ptr[n];
    const int end = g_row_ptr[n + 1];

    const float4* in4 = (const float4*)h_in;

    float4 acc = make_float4(0.f, 0.f, 0.f, 0.f);

    for (int base = blk_beg; base < blk_end; base += GCHUNK) {
        // Coalesced block-wide index staging.
        if (base + tid < blk_end)
            s_idx[tid] = __ldg(&src[base + tid]);
        __syncthreads();

        const int hi = min(end, base + GCHUNK);
        int e = max(beg, base) + half;    // halves take alternating parity

        // 4 edges per half-thread in flight (8 warp-wide).
        for (; e + 6 < hi; e += 8) {
            const int i0 = s_idx[e     - base];
            const int i1 = s_idx[e + 2 - base];
            const int i2 = s_idx[e + 4 - base];
            const int i3 = s_idx[e + 6 - base];
            float4 a0 = __ldg(&in4[(size_t)i0 * 16 + quad]);
            float4 a1 = __ldg(&in4[(size_t)i1 * 16 + quad]);
            float4 a2 = __ldg(&in4[(size_t)i2 * 16 + quad]);
            float4 a3 = __ldg(&in4[(size_t)i3 * 16 + quad]);
            acc.x += (a0.x + a1.x) + (a2.x + a3.x);
            acc.y += (a0.y + a1.y) + (a2.y + a3.y);
            acc.z += (a0.z + a1.z) + (a2.z + a3.z);
            acc.w += (a0.w + a1.w) + (a2.w + a3.w);
        }
        // tail: at most 3 edges per half, stride 2
        for (; e < hi; e += 2) {
            float4 a = __ldg(&in4[(size_t)s_idx[e - base] * 16 + quad]);
            acc.x += a.x; acc.y += a.y; acc.z += a.z; acc.w += a.w;
        }
        __syncthreads();
    }

    // merge the two halves of the warp
    acc.x += __shfl_down_sync(0xffffffffu, acc.x, 16);
    acc.y += __shfl_down_sync(0xffffffffu, acc.y, 16);
    acc.z += __shfl_down_sync(0xffffffffu, acc.z, 16);
    acc.w += __shfl_down_sync(0xffffffffu, acc.w, 16);

    if (half == 0)
        ((float4*)h_out)[(size_t)n * 16 + quad] = acc;
}

extern "C" void kernel_launch(void* const* d_in, const int* in_sizes, int n_in,
                              void* d_out, int out_size) {
    const int*   src      = (const int*)d_in[0];
    const int*   dst      = (const int*)d_in[1];
    const float* features = (const float*)d_in[2];
    const float* W1       = (const float*)d_in[3];
    const float* W2       = (const float*)d_in[4];
    const float* W3       = (const float*)d_in[5];
    float*       out      = (float*)d_out;

    float* t0; float* t1;
    cudaGetSymbolAddress((void**)&t0, g_t0);
    cudaGetSymbolAddress((void**)&t1, g_t1);

    build_row_ptr_kernel<<<(N_NODES + 1 + 255) / 256, 256>>>(dst);
    wc_kernel<<<DIN, DIN>>>(W1, W2, W3);

    gemm_fwc_kernel<<<N_NODES / 64, 256>>>(features, t0);

    const int gblocks = N_NODES / 8;   // 5000
    gather64_kernel<<<gblocks, 256>>>(src, t0, t1);
    gather64_kernel<<<gblocks, 256>>>(src, t1, t0);
    gather64_kernel<<<gblocks, 256>>>(src, t0, out);
}